// round 6
// baseline (speedup 1.0000x reference)
#include <cuda_runtime.h>
#include <cstdint>

#define Bn 4
#define Tn 2048
#define Cn 1024
#define Hn 16
#define Dn 64

// Scratch in [B, H, T, D] layout (fp32)
__device__ float g_Q[Bn * Hn * Tn * Dn];
__device__ float g_K[Bn * Hn * Tn * Dn];
__device__ float g_V[Bn * Hn * Tn * Dn];
__device__ float g_A[Bn * Hn * Tn * Dn];

__device__ __forceinline__ unsigned f2tf(float f) {
    unsigned u;
    asm("cvt.rna.tf32.f32 %0, %1;" : "=r"(u) : "f"(f));
    return u;
}

__device__ __forceinline__ void mma_tf32(float* c, const unsigned* a, const unsigned* b) {
    asm volatile(
        "mma.sync.aligned.m16n8k8.row.col.f32.tf32.tf32.f32 "
        "{%0,%1,%2,%3}, {%4,%5,%6,%7}, {%8,%9}, {%0,%1,%2,%3};\n"
        : "+f"(c[0]), "+f"(c[1]), "+f"(c[2]), "+f"(c[3])
        : "r"(a[0]), "r"(a[1]), "r"(a[2]), "r"(a[3]), "r"(b[0]), "r"(b[1]));
}

// ldmatrix x4 on tf32 data viewed as b16 pairs (non-trans only).
__device__ __forceinline__ void ldsm_x4(unsigned* r, uint32_t addr) {
    asm volatile(
        "ldmatrix.sync.aligned.m8n8.x4.shared.b16 {%0,%1,%2,%3}, [%4];"
        : "=r"(r[0]), "=r"(r[1]), "=r"(r[2]), "=r"(r[3]) : "r"(addr));
}

// ---------------------------------------------------------------------------
// QKV projection: Y = X @ W -> [B,H,T,D]. 128x128 tile, BK=16, 8 warps
// (warp 64x32). Double-buffered smem, vectorized STS, LDSM A-frags.
// ---------------------------------------------------------------------------
__global__ __launch_bounds__(256, 2) void qkv_mma_kernel(
    const float* __restrict__ X,
    const float* __restrict__ Wq,
    const float* __restrict__ Wk,
    const float* __restrict__ Wv)
{
    __shared__ unsigned As[2][128][20];   // [m][k] tf32, row-major
    __shared__ unsigned Bs[2][16][136];   // [k][n] tf32

    const int z = blockIdx.z;
    const float* __restrict__ W = (z == 0) ? Wq : (z == 1) ? Wk : Wv;
    float* __restrict__ Y = (z == 0) ? g_Q : (z == 1) ? g_K : g_V;

    const int tid = threadIdx.x;
    const int lane = tid & 31, wid = tid >> 5;
    const int g = lane >> 2, t = lane & 3;
    const int warpm = wid >> 2, warpn = wid & 3;
    const int m0 = blockIdx.y << 7, n0 = blockIdx.x << 7;

    const int rowA = tid >> 2, kq = tid & 3;
    const int krow = tid >> 5, nq = tid & 31;

    float4 ra0, ra1, rb0, rb1;

    auto ldg = [&](int k0) {
        ra0 = *(const float4*)&X[(size_t)(m0 + rowA) * Cn + k0 + kq * 4];
        ra1 = *(const float4*)&X[(size_t)(m0 + rowA + 64) * Cn + k0 + kq * 4];
        rb0 = *(const float4*)&W[(size_t)(k0 + krow) * Cn + n0 + nq * 4];
        rb1 = *(const float4*)&W[(size_t)(k0 + krow + 8) * Cn + n0 + nq * 4];
    };
    auto sts = [&](int stg) {
        uint4 u;
        u.x = f2tf(ra0.x); u.y = f2tf(ra0.y); u.z = f2tf(ra0.z); u.w = f2tf(ra0.w);
        *(uint4*)&As[stg][rowA][kq * 4] = u;
        u.x = f2tf(ra1.x); u.y = f2tf(ra1.y); u.z = f2tf(ra1.z); u.w = f2tf(ra1.w);
        *(uint4*)&As[stg][rowA + 64][kq * 4] = u;
        u.x = f2tf(rb0.x); u.y = f2tf(rb0.y); u.z = f2tf(rb0.z); u.w = f2tf(rb0.w);
        *(uint4*)&Bs[stg][krow][nq * 4] = u;
        u.x = f2tf(rb1.x); u.y = f2tf(rb1.y); u.z = f2tf(rb1.z); u.w = f2tf(rb1.w);
        *(uint4*)&Bs[stg][krow + 8][nq * 4] = u;
    };

    float c[4][4][4] = {};

    ldg(0);
    sts(0);
    ldg(16);
    __syncthreads();

    // LDSM lane geometry for A m16k8 fragments
    const unsigned a_lrow = (lane & 7) + (((lane >> 3) & 1) << 3);  // 0..15
    const unsigned a_lcol = (lane >> 4) << 2;                       // 0 or 4
    const uint32_t aBase = (uint32_t)__cvta_generic_to_shared(&As[0][0][0]);
    const int boffn = warpn * 32 + g;

    for (int it = 0; it < Cn / 16; ++it) {
        const int cur = it & 1;
        if (it + 1 < Cn / 16) sts(cur ^ 1);
        if (it + 2 < Cn / 16) ldg((it + 2) << 4);

#pragma unroll
        for (int ks = 0; ks < 2; ks++) {
            const int kk = ks << 3;
            unsigned b0[4], b1[4];
#pragma unroll
            for (int nj = 0; nj < 4; nj++) {
                b0[nj] = Bs[cur][kk + t][boffn + nj * 8];
                b1[nj] = Bs[cur][kk + t + 4][boffn + nj * 8];
            }
#pragma unroll
            for (int mi = 0; mi < 4; mi++) {
                unsigned a[4];
                const uint32_t ad = aBase +
                    4u * (cur * 2560 + (warpm * 64 + mi * 16 + a_lrow) * 20 + kk + a_lcol);
                ldsm_x4(a, ad);
#pragma unroll
                for (int nj = 0; nj < 4; nj++) {
                    unsigned bb[2] = {b0[nj], b1[nj]};
                    mma_tf32(c[mi][nj], a, bb);
                }
            }
        }
        __syncthreads();
    }

    // write [B,H,T,D]
#pragma unroll
    for (int mi = 0; mi < 4; mi++) {
#pragma unroll
        for (int r = 0; r < 2; r++) {
            const int row = m0 + warpm * 64 + mi * 16 + g + 8 * r;
            const int b_ = row >> 11, t_ = row & (Tn - 1);
#pragma unroll
            for (int nj = 0; nj < 4; nj++) {
                const int n = n0 + warpn * 32 + nj * 8 + 2 * t;
                const int h = n >> 6, d = n & 63;
                float2 v = {c[mi][nj][2 * r], c[mi][nj][2 * r + 1]};
                *(float2*)&Y[(size_t)((b_ * Hn + h) * Tn + t_) * Dn + d] = v;
            }
        }
    }
}

// ---------------------------------------------------------------------------
// Flash attention: Br=Bc=64, 4 warps, Q in registers, tf32 mma.
//   Ks [key][d]  pitch 68 (row-major; col-major B operand for S)  — LDSM
//   Vs [key][d'] pitch 68, d' = (d&7)*8 + (d>>3)                  — vec LDS
//   Ps [q][key]  pitch 68 (row-major A operand for O)             — LDSM
// ---------------------------------------------------------------------------
#define PF 68
#define FLASH_SMEM_BYTES (3 * 64 * PF * 4)

__global__ __launch_bounds__(128) void flash_mma_kernel()
{
    extern __shared__ unsigned smf[];
    unsigned* Ks = smf;
    unsigned* Vs = smf + 64 * PF;
    unsigned* Ps = smf + 2 * 64 * PF;

    const int qb = blockIdx.x;
    const int h = blockIdx.y, b = blockIdx.z;
    const int tid = threadIdx.x;
    const int lane = tid & 31, wid = tid >> 5;
    const int g = lane >> 2, t = lane & 3;
    const int q0 = qb << 6;
    const int qrow = (wid << 4) + g;

    const size_t base = (size_t)((b * Hn + h) * Tn) * Dn;
    const float* __restrict__ Qg = g_Q + base;
    const float* __restrict__ Kg = g_K + base;
    const float* __restrict__ Vg = g_V + base;

    const int lrow = tid >> 4;          // 0..7
    const int lc = (tid & 15) * 4;      // 0..60

    // stage Q into Ks (vector STS), lift to registers
#pragma unroll
    for (int i = 0; i < 8; i++) {
        const int row = lrow + i * 8;
        float4 v = *(const float4*)&Qg[(size_t)(q0 + row) * Dn + lc];
        uint4 u = {f2tf(v.x), f2tf(v.y), f2tf(v.z), f2tf(v.w)};
        *(uint4*)&Ks[row * PF + lc] = u;
    }
    __syncthreads();

    unsigned qa[8][4];
#pragma unroll
    for (int ks = 0; ks < 8; ks++) {
        qa[ks][0] = Ks[qrow * PF + ks * 8 + t];
        qa[ks][1] = Ks[(qrow + 8) * PF + ks * 8 + t];
        qa[ks][2] = Ks[qrow * PF + ks * 8 + t + 4];
        qa[ks][3] = Ks[(qrow + 8) * PF + ks * 8 + t + 4];
    }
    __syncthreads();

    const uint32_t ksBase = (uint32_t)__cvta_generic_to_shared(Ks);
    const uint32_t psBase = (uint32_t)__cvta_generic_to_shared(Ps);
    // K B-frag LDSM geometry: 4 matrices = (b0,b1) of ks=2j and 2j+1
    const unsigned kb_row = lane & 7;
    const unsigned kb_col = (lane >> 3) << 2;     // 0,4,8,12
    // P A-frag LDSM geometry
    const unsigned pa_row = (lane & 7) + (((lane >> 3) & 1) << 3);
    const unsigned pa_col = (lane >> 4) << 2;

    float o[8][4] = {};
    float mv0 = -1e30f, mv1 = -1e30f, l0 = 0.0f, l1 = 0.0f;

    for (int kb = 0; kb <= qb; kb++) {
        const int k0 = kb << 6;

        // ---- load K (vector), V (permuted scalar) ----
#pragma unroll
        for (int i = 0; i < 8; i++) {
            const int row = lrow + i * 8;
            float4 kv = *(const float4*)&Kg[(size_t)(k0 + row) * Dn + lc];
            uint4 uk = {f2tf(kv.x), f2tf(kv.y), f2tf(kv.z), f2tf(kv.w)};
            *(uint4*)&Ks[row * PF + lc] = uk;
            float4 vv = *(const float4*)&Vg[(size_t)(k0 + row) * Dn + lc];
            const int d0 = lc, d1 = lc + 1, d2 = lc + 2, d3 = lc + 3;
            Vs[row * PF + ((d0 & 7) << 3) + (d0 >> 3)] = f2tf(vv.x);
            Vs[row * PF + ((d1 & 7) << 3) + (d1 >> 3)] = f2tf(vv.y);
            Vs[row * PF + ((d2 & 7) << 3) + (d2 >> 3)] = f2tf(vv.z);
            Vs[row * PF + ((d3 & 7) << 3) + (d3 >> 3)] = f2tf(vv.w);
        }
        __syncthreads();

        // ---- S = Q @ K^T ----
        float s[8][4] = {};
#pragma unroll
        for (int nj = 0; nj < 8; nj++) {
            unsigned kbf[4][4];
#pragma unroll
            for (int j = 0; j < 4; j++) {
                const uint32_t ad = ksBase +
                    4u * ((nj * 8 + kb_row) * PF + j * 16 + kb_col);
                ldsm_x4(kbf[j], ad);
            }
#pragma unroll
            for (int ks = 0; ks < 8; ks++) {
                unsigned bb[2] = {kbf[ks >> 1][(ks & 1) * 2],
                                  kbf[ks >> 1][(ks & 1) * 2 + 1]};
                mma_tf32(s[nj], qa[ks], bb);
            }
        }

        // ---- scale + causal mask ----
        const bool diag = (kb == qb);
#pragma unroll
        for (int nj = 0; nj < 8; nj++) {
#pragma unroll
            for (int e = 0; e < 4; e++) s[nj][e] *= 0.125f;
            if (diag) {
                const int col0 = nj * 8 + 2 * t, col1 = col0 + 1;
                if (col0 > qrow) s[nj][0] = -1e30f;
                if (col1 > qrow) s[nj][1] = -1e30f;
                if (col0 > qrow + 8) s[nj][2] = -1e30f;
                if (col1 > qrow + 8) s[nj][3] = -1e30f;
            }
        }

        // ---- online softmax ----
        float mt0 = -1e30f, mt1 = -1e30f;
#pragma unroll
        for (int nj = 0; nj < 8; nj++) {
            mt0 = fmaxf(mt0, fmaxf(s[nj][0], s[nj][1]));
            mt1 = fmaxf(mt1, fmaxf(s[nj][2], s[nj][3]));
        }
        mt0 = fmaxf(mt0, __shfl_xor_sync(0xffffffffu, mt0, 1));
        mt0 = fmaxf(mt0, __shfl_xor_sync(0xffffffffu, mt0, 2));
        mt1 = fmaxf(mt1, __shfl_xor_sync(0xffffffffu, mt1, 1));
        mt1 = fmaxf(mt1, __shfl_xor_sync(0xffffffffu, mt1, 2));

        const float mn0 = fmaxf(mv0, mt0);
        const float mn1 = fmaxf(mv1, mt1);
        float sum0 = 0.0f, sum1 = 0.0f;
#pragma unroll
        for (int nj = 0; nj < 8; nj++) {
            float p0 = __expf(s[nj][0] - mn0);
            float p1 = __expf(s[nj][1] - mn0);
            float p2 = __expf(s[nj][2] - mn1);
            float p3 = __expf(s[nj][3] - mn1);
            sum0 += p0 + p1;
            sum1 += p2 + p3;
            uint2 w0 = {f2tf(p0), f2tf(p1)};
            *(uint2*)&Ps[qrow * PF + nj * 8 + 2 * t] = w0;
            uint2 w1 = {f2tf(p2), f2tf(p3)};
            *(uint2*)&Ps[(qrow + 8) * PF + nj * 8 + 2 * t] = w1;
        }
        sum0 += __shfl_xor_sync(0xffffffffu, sum0, 1);
        sum0 += __shfl_xor_sync(0xffffffffu, sum0, 2);
        sum1 += __shfl_xor_sync(0xffffffffu, sum1, 1);
        sum1 += __shfl_xor_sync(0xffffffffu, sum1, 2);

        const float cf0 = __expf(mv0 - mn0);
        const float cf1 = __expf(mv1 - mn1);
        l0 = l0 * cf0 + sum0;
        l1 = l1 * cf1 + sum1;
        mv0 = mn0;
        mv1 = mn1;
#pragma unroll
        for (int nj = 0; nj < 8; nj++) {
            o[nj][0] *= cf0; o[nj][1] *= cf0;
            o[nj][2] *= cf1; o[nj][3] *= cf1;
        }
        __syncwarp();

        // ---- O += P @ V ----
#pragma unroll
        for (int ks = 0; ks < 8; ks++) {
            unsigned pa[4];
            ldsm_x4(pa, psBase + 4u * ((wid * 16 + pa_row) * PF + ks * 8 + pa_col));
            unsigned v0[8], v1[8];
            *(uint4*)&v0[0] = *(const uint4*)&Vs[(ks * 8 + t) * PF + g * 8];
            *(uint4*)&v0[4] = *(const uint4*)&Vs[(ks * 8 + t) * PF + g * 8 + 4];
            *(uint4*)&v1[0] = *(const uint4*)&Vs[(ks * 8 + t + 4) * PF + g * 8];
            *(uint4*)&v1[4] = *(const uint4*)&Vs[(ks * 8 + t + 4) * PF + g * 8 + 4];
#pragma unroll
            for (int nj = 0; nj < 8; nj++) {
                unsigned bb[2] = {v0[nj], v1[nj]};
                mma_tf32(o[nj], pa, bb);
            }
        }
        __syncthreads();
    }

    // ---- normalize + write g_A ----
    float* __restrict__ Ag = g_A + base;
    const float inv0 = 1.0f / l0, inv1 = 1.0f / l1;
#pragma unroll
    for (int nj = 0; nj < 8; nj++) {
        const int d = nj * 8 + 2 * t;
        float2 v0 = {o[nj][0] * inv0, o[nj][1] * inv0};
        *(float2*)&Ag[(size_t)(q0 + qrow) * Dn + d] = v0;
        float2 v1 = {o[nj][2] * inv1, o[nj][3] * inv1};
        *(float2*)&Ag[(size_t)(q0 + qrow + 8) * Dn + d] = v1;
    }
}

// ---------------------------------------------------------------------------
// Output projection: out = A @ Wo + bo (A gathered from [B,H,T,D])
// ---------------------------------------------------------------------------
__global__ __launch_bounds__(256, 2) void oproj_mma_kernel(
    const float* __restrict__ Wo,
    const float* __restrict__ bo,
    float* __restrict__ out)
{
    __shared__ unsigned As[2][128][20];
    __shared__ unsigned Bs[2][16][136];

    const int tid = threadIdx.x;
    const int lane = tid & 31, wid = tid >> 5;
    const int g = lane >> 2, t = lane & 3;
    const int warpm = wid >> 2, warpn = wid & 3;
    const int m0 = blockIdx.y << 7, n0 = blockIdx.x << 7;

    const int rowA = tid >> 2, kq = tid & 3;
    const int krow = tid >> 5, nq = tid & 31;

    const int mA0 = m0 + rowA, mA1 = m0 + rowA + 64;
    const int ab0 = mA0 >> 11, at0 = mA0 & (Tn - 1);
    const int ab1 = mA1 >> 11, at1 = mA1 & (Tn - 1);

    float4 ra0, ra1, rb0, rb1;

    auto loadA = [&](int bb, int tt, int k) {
        const int hh = k >> 6, dd = k & 63;
        return *(const float4*)&g_A[(size_t)((bb * Hn + hh) * Tn + tt) * Dn + dd];
    };
    auto ldg = [&](int k0) {
        ra0 = loadA(ab0, at0, k0 + kq * 4);
        ra1 = loadA(ab1, at1, k0 + kq * 4);
        rb0 = *(const float4*)&Wo[(size_t)(k0 + krow) * Cn + n0 + nq * 4];
        rb1 = *(const float4*)&Wo[(size_t)(k0 + krow + 8) * Cn + n0 + nq * 4];
    };
    auto sts = [&](int stg) {
        uint4 u;
        u.x = f2tf(ra0.x); u.y = f2tf(ra0.y); u.z = f2tf(ra0.z); u.w = f2tf(ra0.w);
        *(uint4*)&As[stg][rowA][kq * 4] = u;
        u.x = f2tf(ra1.x); u.y = f2tf(ra1.y); u.z = f2tf(ra1.z); u.w = f2tf(ra1.w);
        *(uint4*)&As[stg][rowA + 64][kq * 4] = u;
        u.x = f2tf(rb0.x); u.y = f2tf(rb0.y); u.z = f2tf(rb0.z); u.w = f2tf(rb0.w);
        *(uint4*)&Bs[stg][krow][nq * 4] = u;
        u.x = f2tf(rb1.x); u.y = f2tf(rb1.y); u.z = f2tf(rb1.z); u.w = f2tf(rb1.w);
        *(uint4*)&Bs[stg][krow + 8][nq * 4] = u;
    };

    float c[4][4][4] = {};

    ldg(0);
    sts(0);
    ldg(16);
    __syncthreads();

    const unsigned a_lrow = (lane & 7) + (((lane >> 3) & 1) << 3);
    const unsigned a_lcol = (lane >> 4) << 2;
    const uint32_t aBase = (uint32_t)__cvta_generic_to_shared(&As[0][0][0]);
    const int boffn = warpn * 32 + g;

    for (int it = 0; it < Cn / 16; ++it) {
        const int cur = it & 1;
        if (it + 1 < Cn / 16) sts(cur ^ 1);
        if (it + 2 < Cn / 16) ldg((it + 2) << 4);

#pragma unroll
        for (int ks = 0; ks < 2; ks++) {
            const int kk = ks << 3;
            unsigned b0[4], b1[4];
#pragma unroll
            for (int nj = 0; nj < 4; nj++) {
                b0[nj] = Bs[cur][kk + t][boffn + nj * 8];
                b1[nj] = Bs[cur][kk + t + 4][boffn + nj * 8];
            }
#pragma unroll
            for (int mi = 0; mi < 4; mi++) {
                unsigned a[4];
                const uint32_t ad = aBase +
                    4u * (cur * 2560 + (warpm * 64 + mi * 16 + a_lrow) * 20 + kk + a_lcol);
                ldsm_x4(a, ad);
#pragma unroll
                for (int nj = 0; nj < 4; nj++) {
                    unsigned bb[2] = {b0[nj], b1[nj]};
                    mma_tf32(c[mi][nj], a, bb);
                }
            }
        }
        __syncthreads();
    }

#pragma unroll
    for (int mi = 0; mi < 4; mi++) {
#pragma unroll
        for (int r = 0; r < 2; r++) {
            const int row = m0 + warpm * 64 + mi * 16 + g + 8 * r;
#pragma unroll
            for (int nj = 0; nj < 4; nj++) {
                const int n = n0 + warpn * 32 + nj * 8 + 2 * t;
                float2 bias = *(const float2*)&bo[n];
                float2 v = {c[mi][nj][2 * r] + bias.x, c[mi][nj][2 * r + 1] + bias.y};
                *(float2*)&out[(size_t)row * Cn + n] = v;
            }
        }
    }
}

// ---------------------------------------------------------------------------
extern "C" void kernel_launch(void* const* d_in, const int* in_sizes, int n_in,
                              void* d_out, int out_size)
{
    const float* x  = (const float*)d_in[0];
    const float* Wq = (const float*)d_in[1];
    const float* Wk = (const float*)d_in[2];
    const float* Wv = (const float*)d_in[3];
    const float* Wo = (const float*)d_in[4];
    const float* bo = (const float*)d_in[5];
    float* out = (float*)d_out;

    cudaFuncSetAttribute(flash_mma_kernel,
                         cudaFuncAttributeMaxDynamicSharedMemorySize, FLASH_SMEM_BYTES);

    dim3 gq(Cn / 128, (Bn * Tn) / 128, 3);
    qkv_mma_kernel<<<gq, 256>>>(x, Wq, Wk, Wv);

    dim3 ga(Tn / 64, Hn, Bn);
    flash_mma_kernel<<<ga, 128, FLASH_SMEM_BYTES>>>();

    dim3 go(Cn / 128, (Bn * Tn) / 128);
    oproj_mma_kernel<<<go, 256>>>(Wo, bo, out);
}

// round 8
// speedup vs baseline: 1.6195x; 1.6195x over previous
#include <cuda_runtime.h>
#include <cuda_fp16.h>
#include <cstdint>

#define Bn 4
#define Tn 2048
#define Cn 1024
#define Hn 16
#define Dn 64

// Inter-kernel tensors in half, [B,H,T,D]
__device__ __half g_Q[Bn * Hn * Tn * Dn];
__device__ __half g_K[Bn * Hn * Tn * Dn];
__device__ __half g_V[Bn * Hn * Tn * Dn];
__device__ __half g_A[Bn * Hn * Tn * Dn];
// Pre-transposed half weights: g_Wt[z][n*Cn + k] = half(W_z[k][n])
__device__ __half g_Wt[4][Cn * Cn];

__device__ __forceinline__ unsigned h2u(float a, float b) {
    __half2 h = __floats2half2_rn(a, b);
    return *(unsigned*)&h;
}
__device__ __forceinline__ void mma_f16(float* c, const unsigned* a, const unsigned* b) {
    asm volatile(
        "mma.sync.aligned.m16n8k16.row.col.f32.f16.f16.f32 "
        "{%0,%1,%2,%3}, {%4,%5,%6,%7}, {%8,%9}, {%0,%1,%2,%3};\n"
        : "+f"(c[0]), "+f"(c[1]), "+f"(c[2]), "+f"(c[3])
        : "r"(a[0]), "r"(a[1]), "r"(a[2]), "r"(a[3]), "r"(b[0]), "r"(b[1]));
}
__device__ __forceinline__ void ldsm_x4(unsigned* r, uint32_t addr) {
    asm volatile(
        "ldmatrix.sync.aligned.m8n8.x4.shared.b16 {%0,%1,%2,%3}, [%4];"
        : "=r"(r[0]), "=r"(r[1]), "=r"(r[2]), "=r"(r[3]) : "r"(addr));
}
__device__ __forceinline__ void ldsm_x4_t(unsigned* r, uint32_t addr) {
    asm volatile(
        "ldmatrix.sync.aligned.m8n8.x4.trans.shared.b16 {%0,%1,%2,%3}, [%4];"
        : "=r"(r[0]), "=r"(r[1]), "=r"(r[2]), "=r"(r[3]) : "r"(addr));
}

// ---------------------------------------------------------------------------
// One-shot weight transpose: g_Wt[z][n][k] = half(W_z[k][n])
// ---------------------------------------------------------------------------
__global__ __launch_bounds__(256) void wtrans_kernel(
    const float* __restrict__ Wq, const float* __restrict__ Wk,
    const float* __restrict__ Wv, const float* __restrict__ Wo)
{
    __shared__ float tile[32][33];
    const int z = blockIdx.z;
    const float* __restrict__ W = (z == 0) ? Wq : (z == 1) ? Wk : (z == 2) ? Wv : Wo;
    const int x0 = blockIdx.x << 5, y0 = blockIdx.y << 5;   // x=n, y=k
    const int tx = threadIdx.x, ty = threadIdx.y;
#pragma unroll
    for (int j = 0; j < 32; j += 8)
        tile[ty + j][tx] = W[(size_t)(y0 + ty + j) * Cn + x0 + tx];
    __syncthreads();
#pragma unroll
    for (int j = 0; j < 32; j += 8)
        g_Wt[z][(size_t)(x0 + ty + j) * Cn + y0 + tx] = __float2half_rn(tile[tx][ty + j]);
}

// ---------------------------------------------------------------------------
// fp16 GEMM core: block 128x128, BK=32, 8 warps (warp 64x32), double-buffered.
// As[stage][m][k] half pitch 40; Bs[stage][n][k] half pitch 40 (from Wt).
// ---------------------------------------------------------------------------
#define QP 40

__global__ __launch_bounds__(256, 2) void qkv_h_kernel(const float* __restrict__ X)
{
    __shared__ __half As[2][128][QP];
    __shared__ __half Bs[2][128][QP];

    const int z = blockIdx.z;
    const __half* __restrict__ Wt = g_Wt[z];
    __half* __restrict__ Y = (z == 0) ? g_Q : (z == 1) ? g_K : g_V;

    const int tid = threadIdx.x;
    const int lane = tid & 31, wid = tid >> 5;
    const int g = lane >> 2, t = lane & 3;
    const int warpm = wid >> 2, warpn = wid & 3;
    const int m0 = blockIdx.y << 7, n0 = blockIdx.x << 7;

    const int row = tid >> 1, e = tid & 1;   // staging: 2 threads per row

    float4 ra[4];
    uint4 rb[2];
    auto ldg = [&](int k0) {
#pragma unroll
        for (int i = 0; i < 4; i++)
            ra[i] = *(const float4*)&X[(size_t)(m0 + row) * Cn + k0 + e * 16 + i * 4];
        const uint4* bp = (const uint4*)&Wt[(size_t)(n0 + row) * Cn + k0 + e * 16];
        rb[0] = bp[0];
        rb[1] = bp[1];
    };
    auto sts = [&](int stg) {
        uint4 u0 = {h2u(ra[0].x, ra[0].y), h2u(ra[0].z, ra[0].w),
                    h2u(ra[1].x, ra[1].y), h2u(ra[1].z, ra[1].w)};
        uint4 u1 = {h2u(ra[2].x, ra[2].y), h2u(ra[2].z, ra[2].w),
                    h2u(ra[3].x, ra[3].y), h2u(ra[3].z, ra[3].w)};
        *(uint4*)&As[stg][row][e * 16] = u0;
        *(uint4*)&As[stg][row][e * 16 + 8] = u1;
        *(uint4*)&Bs[stg][row][e * 16] = rb[0];
        *(uint4*)&Bs[stg][row][e * 16 + 8] = rb[1];
    };

    float c[4][4][4] = {};

    ldg(0);
    sts(0);
    ldg(32);
    __syncthreads();

    const unsigned a_lr = (lane & 7) + (((lane >> 3) & 1) << 3);
    const unsigned a_lc = ((lane >> 4) & 1) << 3;
    const unsigned b_lr = (((lane >> 4) & 1) << 3) + (lane & 7);
    const unsigned b_lc = ((lane >> 3) & 1) << 3;
    const uint32_t aBase = (uint32_t)__cvta_generic_to_shared(&As[0][0][0]);
    const uint32_t bBase = (uint32_t)__cvta_generic_to_shared(&Bs[0][0][0]);

    for (int it = 0; it < Cn / 32; ++it) {
        const int cur = it & 1;
        if (it + 1 < Cn / 32) sts(cur ^ 1);
        if (it + 2 < Cn / 32) ldg((it + 2) << 5);

#pragma unroll
        for (int ks = 0; ks < 2; ks++) {
            const int kk = ks << 4;
            unsigned bf[2][4];
#pragma unroll
            for (int p = 0; p < 2; p++) {
                const unsigned rn = warpn * 32 + p * 16 + b_lr;
                ldsm_x4(bf[p], bBase + 2u * (cur * 128 * QP + rn * QP + kk + b_lc));
            }
#pragma unroll
            for (int mi = 0; mi < 4; mi++) {
                unsigned a[4];
                const unsigned rm = warpm * 64 + mi * 16 + a_lr;
                ldsm_x4(a, aBase + 2u * (cur * 128 * QP + rm * QP + kk + a_lc));
#pragma unroll
                for (int nj = 0; nj < 4; nj++) {
                    unsigned bb[2] = {bf[nj >> 1][(nj & 1) * 2],
                                      bf[nj >> 1][(nj & 1) * 2 + 1]};
                    mma_f16(c[mi][nj], a, bb);
                }
            }
        }
        __syncthreads();
    }

    // write [B,H,T,D] half
#pragma unroll
    for (int mi = 0; mi < 4; mi++) {
#pragma unroll
        for (int r = 0; r < 2; r++) {
            const int mrow = m0 + warpm * 64 + mi * 16 + g + 8 * r;
            const int b_ = mrow >> 11, t_ = mrow & (Tn - 1);
#pragma unroll
            for (int nj = 0; nj < 4; nj++) {
                const int n = n0 + warpn * 32 + nj * 8 + 2 * t;
                const int h = n >> 6, d = n & 63;
                __half2 hv = __floats2half2_rn(c[mi][nj][2 * r], c[mi][nj][2 * r + 1]);
                *(__half2*)&Y[(size_t)((b_ * Hn + h) * Tn + t_) * Dn + d] = hv;
            }
        }
    }
}

// ---------------------------------------------------------------------------
// oproj: out = A @ Wo + bo (fp32 out). A gathered from g_A (half).
// ---------------------------------------------------------------------------
__global__ __launch_bounds__(256, 2) void oproj_h_kernel(
    const float* __restrict__ bo, float* __restrict__ out)
{
    __shared__ __half As[2][128][QP];
    __shared__ __half Bs[2][128][QP];
    const __half* __restrict__ Wt = g_Wt[3];

    const int tid = threadIdx.x;
    const int lane = tid & 31, wid = tid >> 5;
    const int g = lane >> 2, t = lane & 3;
    const int warpm = wid >> 2, warpn = wid & 3;
    const int m0 = blockIdx.y << 7, n0 = blockIdx.x << 7;

    const int row = tid >> 1, e = tid & 1;
    const int m = m0 + row;
    const int mb = m >> 11, mt = m & (Tn - 1);

    uint4 ra[2], rb[2];
    auto ldg = [&](int k0) {
        const int hh = k0 >> 6, dd = (k0 & 63) + e * 16;
        const uint4* ap = (const uint4*)&g_A[(size_t)((mb * Hn + hh) * Tn + mt) * Dn + dd];
        ra[0] = ap[0];
        ra[1] = ap[1];
        const uint4* bp = (const uint4*)&Wt[(size_t)(n0 + row) * Cn + k0 + e * 16];
        rb[0] = bp[0];
        rb[1] = bp[1];
    };
    auto sts = [&](int stg) {
        *(uint4*)&As[stg][row][e * 16] = ra[0];
        *(uint4*)&As[stg][row][e * 16 + 8] = ra[1];
        *(uint4*)&Bs[stg][row][e * 16] = rb[0];
        *(uint4*)&Bs[stg][row][e * 16 + 8] = rb[1];
    };

    float c[4][4][4] = {};

    ldg(0);
    sts(0);
    ldg(32);
    __syncthreads();

    const unsigned a_lr = (lane & 7) + (((lane >> 3) & 1) << 3);
    const unsigned a_lc = ((lane >> 4) & 1) << 3;
    const unsigned b_lr = (((lane >> 4) & 1) << 3) + (lane & 7);
    const unsigned b_lc = ((lane >> 3) & 1) << 3;
    const uint32_t aBase = (uint32_t)__cvta_generic_to_shared(&As[0][0][0]);
    const uint32_t bBase = (uint32_t)__cvta_generic_to_shared(&Bs[0][0][0]);

    for (int it = 0; it < Cn / 32; ++it) {
        const int cur = it & 1;
        if (it + 1 < Cn / 32) sts(cur ^ 1);
        if (it + 2 < Cn / 32) ldg((it + 2) << 5);

#pragma unroll
        for (int ks = 0; ks < 2; ks++) {
            const int kk = ks << 4;
            unsigned bf[2][4];
#pragma unroll
            for (int p = 0; p < 2; p++) {
                const unsigned rn = warpn * 32 + p * 16 + b_lr;
                ldsm_x4(bf[p], bBase + 2u * (cur * 128 * QP + rn * QP + kk + b_lc));
            }
#pragma unroll
            for (int mi = 0; mi < 4; mi++) {
                unsigned a[4];
                const unsigned rm = warpm * 64 + mi * 16 + a_lr;
                ldsm_x4(a, aBase + 2u * (cur * 128 * QP + rm * QP + kk + a_lc));
#pragma unroll
                for (int nj = 0; nj < 4; nj++) {
                    unsigned bb[2] = {bf[nj >> 1][(nj & 1) * 2],
                                      bf[nj >> 1][(nj & 1) * 2 + 1]};
                    mma_f16(c[mi][nj], a, bb);
                }
            }
        }
        __syncthreads();
    }

#pragma unroll
    for (int mi = 0; mi < 4; mi++) {
#pragma unroll
        for (int r = 0; r < 2; r++) {
            const int mrow = m0 + warpm * 64 + mi * 16 + g + 8 * r;
#pragma unroll
            for (int nj = 0; nj < 4; nj++) {
                const int n = n0 + warpn * 32 + nj * 8 + 2 * t;
                float2 bias = *(const float2*)&bo[n];
                float2 v = {c[mi][nj][2 * r] + bias.x, c[mi][nj][2 * r + 1] + bias.y};
                *(float2*)&out[(size_t)mrow * Cn + n] = v;
            }
        }
    }
}

// ---------------------------------------------------------------------------
// Flash attention fp16: Br=Bc=64, 4 warps, Q frags in registers.
//   Ks [key][d]  half pitch 72 — LDSM (B for S)
//   Vs [key][d]  half pitch 72 — LDSM.trans (B for PV)
//   Ps [q][key]  half pitch 72 — LDSM (A for PV); also Q staging
// ---------------------------------------------------------------------------
#define FP 72

__global__ __launch_bounds__(128) void flash_h_kernel()
{
    __shared__ __half Ks[64][FP];
    __shared__ __half Vs[64][FP];
    __shared__ __half Ps[64][FP];

    const int qb = blockIdx.x;
    const int h = blockIdx.y, b = blockIdx.z;
    const int tid = threadIdx.x;
    const int lane = tid & 31, wid = tid >> 5;
    const int g = lane >> 2, t = lane & 3;
    const int q0 = qb << 6;
    const int qrow = (wid << 4) + g;

    const size_t base = (size_t)((b * Hn + h) * Tn) * Dn;
    const __half* __restrict__ Qg = g_Q + base;
    const __half* __restrict__ Kg = g_K + base;
    const __half* __restrict__ Vg = g_V + base;

    const int srow = tid >> 1, se = tid & 1;   // staging: 2 threads/row, 64B each

    // stage Q into Ps, lift A-fragments to registers
    {
        const uint4* qp = (const uint4*)&Qg[(size_t)(q0 + srow) * Dn + se * 32];
#pragma unroll
        for (int j = 0; j < 4; j++)
            *(uint4*)&Ps[srow][se * 32 + j * 8] = qp[j];
    }
    __syncthreads();

    const unsigned a_lr = (lane & 7) + (((lane >> 3) & 1) << 3);
    const unsigned a_lc = ((lane >> 4) & 1) << 3;
    const uint32_t ksBase = (uint32_t)__cvta_generic_to_shared(&Ks[0][0]);
    const uint32_t vsBase = (uint32_t)__cvta_generic_to_shared(&Vs[0][0]);
    const uint32_t psBase = (uint32_t)__cvta_generic_to_shared(&Ps[0][0]);

    unsigned qa[4][4];
#pragma unroll
    for (int ks = 0; ks < 4; ks++)
        ldsm_x4(qa[ks], psBase + 2u * ((wid * 16 + a_lr) * FP + ks * 16 + a_lc));
    __syncthreads();

    float o[8][4] = {};
    float mv0 = -1e30f, mv1 = -1e30f, l0 = 0.0f, l1 = 0.0f;

    for (int kb = 0; kb <= qb; kb++) {
        const int k0 = kb << 6;
        // stage K, V (pure half copies)
        {
            const uint4* kp = (const uint4*)&Kg[(size_t)(k0 + srow) * Dn + se * 32];
            const uint4* vp = (const uint4*)&Vg[(size_t)(k0 + srow) * Dn + se * 32];
#pragma unroll
            for (int j = 0; j < 4; j++) {
                *(uint4*)&Ks[srow][se * 32 + j * 8] = kp[j];
                *(uint4*)&Vs[srow][se * 32 + j * 8] = vp[j];
            }
        }
        __syncthreads();

        // ---- S = Q @ K^T ----
        float s[8][4] = {};
#pragma unroll
        for (int nj = 0; nj < 8; nj++) {
            unsigned bf[8];
            const uint32_t ad = ksBase + 2u * ((nj * 8 + (lane & 7)) * FP + (lane >> 3) * 8);
            ldsm_x4(bf, ad);
            ldsm_x4(bf + 4, ad + 64);   // +32 halves
#pragma unroll
            for (int ks = 0; ks < 4; ks++) {
                unsigned bb[2] = {bf[2 * ks], bf[2 * ks + 1]};
                mma_f16(s[nj], qa[ks], bb);
            }
        }

        // ---- scale + causal mask ----
        const bool diag = (kb == qb);
#pragma unroll
        for (int nj = 0; nj < 8; nj++) {
#pragma unroll
            for (int e2 = 0; e2 < 4; e2++) s[nj][e2] *= 0.125f;
            if (diag) {
                const int col0 = nj * 8 + 2 * t, col1 = col0 + 1;
                if (col0 > qrow) s[nj][0] = -1e30f;
                if (col1 > qrow) s[nj][1] = -1e30f;
                if (col0 > qrow + 8) s[nj][2] = -1e30f;
                if (col1 > qrow + 8) s[nj][3] = -1e30f;
            }
        }

        // ---- online softmax ----
        float mt0 = -1e30f, mt1 = -1e30f;
#pragma unroll
        for (int nj = 0; nj < 8; nj++) {
            mt0 = fmaxf(mt0, fmaxf(s[nj][0], s[nj][1]));
            mt1 = fmaxf(mt1, fmaxf(s[nj][2], s[nj][3]));
        }
        mt0 = fmaxf(mt0, __shfl_xor_sync(0xffffffffu, mt0, 1));
        mt0 = fmaxf(mt0, __shfl_xor_sync(0xffffffffu, mt0, 2));
        mt1 = fmaxf(mt1, __shfl_xor_sync(0xffffffffu, mt1, 1));
        mt1 = fmaxf(mt1, __shfl_xor_sync(0xffffffffu, mt1, 2));

        const float mn0 = fmaxf(mv0, mt0);
        const float mn1 = fmaxf(mv1, mt1);
        float sum0 = 0.0f, sum1 = 0.0f;
#pragma unroll
        for (int nj = 0; nj < 8; nj++) {
            float p0 = __expf(s[nj][0] - mn0);
            float p1 = __expf(s[nj][1] - mn0);
            float p2 = __expf(s[nj][2] - mn1);
            float p3 = __expf(s[nj][3] - mn1);
            sum0 += p0 + p1;
            sum1 += p2 + p3;
            *(__half2*)&Ps[qrow][nj * 8 + 2 * t] = __floats2half2_rn(p0, p1);
            *(__half2*)&Ps[qrow + 8][nj * 8 + 2 * t] = __floats2half2_rn(p2, p3);
        }
        sum0 += __shfl_xor_sync(0xffffffffu, sum0, 1);
        sum0 += __shfl_xor_sync(0xffffffffu, sum0, 2);
        sum1 += __shfl_xor_sync(0xffffffffu, sum1, 1);
        sum1 += __shfl_xor_sync(0xffffffffu, sum1, 2);

        const float cf0 = __expf(mv0 - mn0);
        const float cf1 = __expf(mv1 - mn1);
        l0 = l0 * cf0 + sum0;
        l1 = l1 * cf1 + sum1;
        mv0 = mn0;
        mv1 = mn1;
#pragma unroll
        for (int nj = 0; nj < 8; nj++) {
            o[nj][0] *= cf0; o[nj][1] *= cf0;
            o[nj][2] *= cf1; o[nj][3] *= cf1;
        }
        __syncwarp();

        // ---- O += P @ V ----
        unsigned pa[4][4];
#pragma unroll
        for (int ks = 0; ks < 4; ks++)
            ldsm_x4(pa[ks], psBase + 2u * ((wid * 16 + a_lr) * FP + ks * 16 + a_lc));
#pragma unroll
        for (int nj = 0; nj < 8; nj++) {
            unsigned vf[8];
            ldsm_x4_t(vf, vsBase + 2u * (lane * FP + nj * 8));
            ldsm_x4_t(vf + 4, vsBase + 2u * ((32 + lane) * FP + nj * 8));
#pragma unroll
            for (int ks = 0; ks < 4; ks++) {
                unsigned bb[2] = {vf[2 * ks], vf[2 * ks + 1]};
                mma_f16(o[nj], pa[ks], bb);
            }
        }
        __syncthreads();
    }

    // ---- normalize + write g_A (half) ----
    __half* __restrict__ Ag = g_A + base;
    const float inv0 = 1.0f / l0, inv1 = 1.0f / l1;
#pragma unroll
    for (int nj = 0; nj < 8; nj++) {
        const int d = nj * 8 + 2 * t;
        *(__half2*)&Ag[(size_t)(q0 + qrow) * Dn + d] =
            __floats2half2_rn(o[nj][0] * inv0, o[nj][1] * inv0);
        *(__half2*)&Ag[(size_t)(q0 + qrow + 8) * Dn + d] =
            __floats2half2_rn(o[nj][2] * inv1, o[nj][3] * inv1);
    }
}

// ---------------------------------------------------------------------------
extern "C" void kernel_launch(void* const* d_in, const int* in_sizes, int n_in,
                              void* d_out, int out_size)
{
    const float* x  = (const float*)d_in[0];
    const float* Wq = (const float*)d_in[1];
    const float* Wk = (const float*)d_in[2];
    const float* Wv = (const float*)d_in[3];
    const float* Wo = (const float*)d_in[4];
    const float* bo = (const float*)d_in[5];
    float* out = (float*)d_out;

    wtrans_kernel<<<dim3(Cn / 32, Cn / 32, 4), dim3(32, 8)>>>(Wq, Wk, Wv, Wo);

    qkv_h_kernel<<<dim3(Cn / 128, (Bn * Tn) / 128, 3), 256>>>(x);

    flash_h_kernel<<<dim3(Tn / 64, Hn, Bn), 128>>>();

    oproj_h_kernel<<<dim3(Cn / 128, (Bn * Tn) / 128), 256>>>(bo, out);
}